// round 1
// baseline (speedup 1.0000x reference)
#include <cuda_runtime.h>

#define NB    16
#define NCP   64
#define NTPL  2048
#define HD    10
#define NSTEP 6
#define DTC   0.2f

// ---- scratch (static device globals; no allocation) ----
__device__ float g_P[NSTEP + 1][NB * NCP * 2];
__device__ float g_Q[NSTEP + 1][NB * NCP * 2];
__device__ float g_X[NB * NTPL * 2];

__device__ __forceinline__ float ftanh(float x) {
    // tanh(x) = 1 - 2/(exp(2x)+1); handles +-inf saturation correctly.
    float e = __expf(2.0f * x);
    return 1.0f - __fdividef(2.0f, e + 1.0f);
}

// ------------------------------------------------------------------
// init: broadcast template -> g_X, control points -> g_P[0], q0 -> g_Q[0]
// ------------------------------------------------------------------
__global__ void init_kernel(const float* __restrict__ q0,
                            const float* __restrict__ tpl,
                            const float* __restrict__ cp) {
    int idx = blockIdx.x * blockDim.x + threadIdx.x;
    if (idx < NB * NTPL * 2) g_X[idx] = tpl[idx & (NTPL * 2 - 1)];
    if (idx < NB * NCP * 2) {
        g_Q[0][idx] = q0[idx];
        g_P[0][idx] = cp[idx & (NCP * 2 - 1)];
    }
}

// ------------------------------------------------------------------
// MLP forward + 2-tangent JVP (tangent dirs = rows da, db of W1)
// ------------------------------------------------------------------
__device__ __forceinline__ void mlp_jac(
    float z0, float z1, float z2, float z3, int da, int db,
    const float* __restrict__ sW1, const float* __restrict__ sb1,
    const float* __restrict__ sW2, const float* __restrict__ sb2,
    const float* __restrict__ sW3, const float* __restrict__ sb3,
    float o[3], float ja[3], float jb[3]) {
    float h1[HD], ta[HD], tb[HD];
#pragma unroll
    for (int n = 0; n < HD; n++) {
        float u = sb1[n] + z0 * sW1[n] + z1 * sW1[10 + n] + z2 * sW1[20 + n] + z3 * sW1[30 + n];
        float h = ftanh(u);
        float g = 1.0f - h * h;
        h1[n] = h;
        ta[n] = g * sW1[da * 10 + n];
        tb[n] = g * sW1[db * 10 + n];
    }
    float u2[HD], s2a[HD], s2b[HD];
#pragma unroll
    for (int m = 0; m < HD; m++) { u2[m] = sb2[m]; s2a[m] = 0.f; s2b[m] = 0.f; }
#pragma unroll
    for (int n = 0; n < HD; n++) {
        float h = h1[n], aa = ta[n], bb = tb[n];
#pragma unroll
        for (int m = 0; m < HD; m++) {
            float w = sW2[n * 10 + m];
            u2[m] += h * w;
            s2a[m] += aa * w;
            s2b[m] += bb * w;
        }
    }
#pragma unroll
    for (int c = 0; c < 3; c++) { o[c] = sb3[c]; ja[c] = 0.f; jb[c] = 0.f; }
#pragma unroll
    for (int m = 0; m < HD; m++) {
        float h = ftanh(u2[m]);
        float g = 1.0f - h * h;
        float aa = s2a[m] * g, bb = s2b[m] * g;
#pragma unroll
        for (int c = 0; c < 3; c++) {
            float w = sW3[m * 3 + c];
            o[c] += h * w;
            ja[c] += aa * w;
            jb[c] += bb * w;
        }
    }
}

// ------------------------------------------------------------------
// shooting step: one block per (batch,a) point; thread j = partner.
//   p' = p + DT * K(p,p) q        (dh_dq)
//   q' = q - DT * dH/dp           (analytic grad)
// ------------------------------------------------------------------
__global__ void shoot_kernel(int k,
    const float* __restrict__ W1, const float* __restrict__ b1,
    const float* __restrict__ W2, const float* __restrict__ b2,
    const float* __restrict__ W3, const float* __restrict__ b3) {
    __shared__ float sW1[40], sb1[10], sW2[100], sb2[10], sW3[30], sb3[3];
    __shared__ float red[2][4];
    int t = threadIdx.x;
    for (int i = t; i < 40; i += 64) sW1[i] = W1[i];
    for (int i = t; i < 100; i += 64) sW2[i] = W2[i];
    for (int i = t; i < 30; i += 64) sW3[i] = W3[i];
    if (t < 10) { sb1[t] = b1[t]; sb2[t] = b2[t]; }
    if (t < 3) sb3[t] = b3[t];
    __syncthreads();

    int blk = blockIdx.x;
    int b = blk >> 6, a = blk & 63;
    const float* P = g_P[k];
    const float* Q = g_Q[k];
    float pax = P[(b * NCP + a) * 2 + 0], pay = P[(b * NCP + a) * 2 + 1];
    float qax = Q[(b * NCP + a) * 2 + 0], qay = Q[(b * NCP + a) * 2 + 1];
    int j = t;
    float pjx = P[(b * NCP + j) * 2 + 0], pjy = P[(b * NCP + j) * 2 + 1];
    float qjx = Q[(b * NCP + j) * 2 + 0], qjy = Q[(b * NCP + j) * 2 + 1];

    float o1[3], d10[3], d11[3];
    mlp_jac(pax, pay, pjx, pjy, 0, 1, sW1, sb1, sW2, sb2, sW3, sb3, o1, d10, d11);
    float o2[3], d22[3], d23[3];
    mlp_jac(pjx, pjy, pax, pay, 2, 3, sW1, sb1, sW2, sb2, sW3, sb3, o2, d22, d23);

    float e1a = __expf(o1[1]), e1b = __expf(o1[2]);
    float e2a = __expf(o2[1]), e2b = __expf(o2[2]);
    float Kxx = 0.5f * (e1a + e2a);
    float Kxy = 0.5f * (o1[0] + o2[0]);
    float Kyy = 0.5f * (e1b + e2b);
    float vqx = Kxx * qjx + Kxy * qjy;
    float vqy = Kxy * qjx + Kyy * qjy;

    float cw = qax * qjy + qay * qjx;
    float uxx = qax * qjx, uyy = qay * qjy;
    float w11 = e1a * uxx, w12 = e1b * uyy;
    float w21 = e2a * uxx, w22 = e2b * uyy;
    float gpx = 0.5f * (cw * d10[0] + w11 * d10[1] + w12 * d10[2]
                      + cw * d22[0] + w21 * d22[1] + w22 * d22[2]);
    float gpy = 0.5f * (cw * d11[0] + w11 * d11[1] + w12 * d11[2]
                      + cw * d23[0] + w21 * d23[1] + w22 * d23[2]);

#pragma unroll
    for (int off = 16; off > 0; off >>= 1) {
        vqx += __shfl_down_sync(0xffffffffu, vqx, off);
        vqy += __shfl_down_sync(0xffffffffu, vqy, off);
        gpx += __shfl_down_sync(0xffffffffu, gpx, off);
        gpy += __shfl_down_sync(0xffffffffu, gpy, off);
    }
    if ((t & 31) == 0) {
        int w = t >> 5;
        red[w][0] = vqx; red[w][1] = vqy; red[w][2] = gpx; red[w][3] = gpy;
    }
    __syncthreads();
    if (t == 0) {
        float VX = red[0][0] + red[1][0];
        float VY = red[0][1] + red[1][1];
        float GX = red[0][2] + red[1][2];
        float GY = red[0][3] + red[1][3];
        float* Pn = g_P[k + 1];
        float* Qn = g_Q[k + 1];
        Pn[(b * NCP + a) * 2 + 0] = pax + DTC * VX;
        Pn[(b * NCP + a) * 2 + 1] = pay + DTC * VY;
        Qn[(b * NCP + a) * 2 + 0] = qax - DTC * GX;
        Qn[(b * NCP + a) * 2 + 1] = qay - DTC * GY;
    }
}

// ------------------------------------------------------------------
// forward MLP, layer-1 preactivation precomputed; W2/W3 in registers
// ------------------------------------------------------------------
__device__ __forceinline__ void mlp_fwd_reg(
    const float u1in[HD],
    const float W2r[100], const float b2r[HD],
    const float W3r[30], const float b3r[3],
    float& o0, float& o1, float& o2) {
    float u2[HD];
#pragma unroll
    for (int m = 0; m < HD; m++) u2[m] = b2r[m];
#pragma unroll
    for (int n = 0; n < HD; n++) {
        float h = ftanh(u1in[n]);
#pragma unroll
        for (int m = 0; m < HD; m++) u2[m] += h * W2r[n * 10 + m];
    }
    o0 = b3r[0]; o1 = b3r[1]; o2 = b3r[2];
#pragma unroll
    for (int m = 0; m < HD; m++) {
        float h = ftanh(u2[m]);
        o0 += h * W3r[m * 3 + 0];
        o1 += h * W3r[m * 3 + 1];
        o2 += h * W3r[m * 3 + 2];
    }
}

// ------------------------------------------------------------------
// flow step: x += DT * K(x, p_k) q_k.  128 thr/block = 32 points x 4 j-splits.
// ------------------------------------------------------------------
__global__ void __launch_bounds__(128, 1) flow_kernel(int k, int last, float* __restrict__ dout,
    const float* __restrict__ W1, const float* __restrict__ b1,
    const float* __restrict__ W2, const float* __restrict__ b2,
    const float* __restrict__ W3, const float* __restrict__ b3) {
    __shared__ float sA[NCP][HD];  // b1 + pj . W1[0:2]  (pj in x-slots)
    __shared__ float sB[NCP][HD];  //      pj . W1[2:4]  (pj in y-slots)
    __shared__ float sQ[NCP][2];
    int t = threadIdx.x;
    int blk = blockIdx.x;
    int b = blk >> 6;
    int pt0 = (blk & 63) << 5;
    const float* P = g_P[k];
    const float* Q = g_Q[k];
    if (t < NCP) {
        float px = P[(b * NCP + t) * 2 + 0], py = P[(b * NCP + t) * 2 + 1];
#pragma unroll
        for (int n = 0; n < HD; n++) {
            sA[t][n] = __ldg(&b1[n]) + px * __ldg(&W1[n]) + py * __ldg(&W1[10 + n]);
            sB[t][n] = px * __ldg(&W1[20 + n]) + py * __ldg(&W1[30 + n]);
        }
        sQ[t][0] = Q[(b * NCP + t) * 2 + 0];
        sQ[t][1] = Q[(b * NCP + t) * 2 + 1];
    }

    // weights resident in registers across the whole j-loop
    float W2r[100];
#pragma unroll
    for (int i = 0; i < 100; i++) W2r[i] = __ldg(&W2[i]);
    float W3r[30];
#pragma unroll
    for (int i = 0; i < 30; i++) W3r[i] = __ldg(&W3[i]);
    float b2r[HD];
#pragma unroll
    for (int i = 0; i < HD; i++) b2r[i] = __ldg(&b2[i]);
    float b3r[3];
#pragma unroll
    for (int i = 0; i < 3; i++) b3r[i] = __ldg(&b3[i]);

    int lp = t >> 2, quarter = t & 3;
    int i0 = pt0 + lp;
    int xoff = (b * NTPL + i0) * 2;
    float xx = g_X[xoff], xy = g_X[xoff + 1];
    float ax[HD], bx[HD];
#pragma unroll
    for (int n = 0; n < HD; n++) {
        ax[n] = __ldg(&b1[n]) + xx * __ldg(&W1[n]) + xy * __ldg(&W1[10 + n]);
        bx[n] = xx * __ldg(&W1[20 + n]) + xy * __ldg(&W1[30 + n]);
    }
    __syncthreads();

    float vx = 0.f, vy = 0.f;
    int jbase = quarter << 4;
#pragma unroll 1
    for (int jj = 0; jj < 16; jj++) {
        int j = jbase + jj;
        float u1[HD];
#pragma unroll
        for (int n = 0; n < HD; n++) u1[n] = ax[n] + sB[j][n];  // m(x, pj)
        float a0, a1, a2;
        mlp_fwd_reg(u1, W2r, b2r, W3r, b3r, a0, a1, a2);
#pragma unroll
        for (int n = 0; n < HD; n++) u1[n] = sA[j][n] + bx[n];  // m(pj, x)
        float c0, c1, c2;
        mlp_fwd_reg(u1, W2r, b2r, W3r, b3r, c0, c1, c2);
        float Kxx = 0.5f * (__expf(a1) + __expf(c1));
        float Kxy = 0.5f * (a0 + c0);
        float Kyy = 0.5f * (__expf(a2) + __expf(c2));
        float qx = sQ[j][0], qy = sQ[j][1];
        vx += Kxx * qx + Kxy * qy;
        vy += Kxy * qx + Kyy * qy;
    }
    // combine the 4 j-splits (adjacent lanes)
    vx += __shfl_xor_sync(0xffffffffu, vx, 1);
    vy += __shfl_xor_sync(0xffffffffu, vy, 1);
    vx += __shfl_xor_sync(0xffffffffu, vx, 2);
    vy += __shfl_xor_sync(0xffffffffu, vy, 2);
    if (quarter == 0) {
        float nx = xx + DTC * vx;
        float ny = xy + DTC * vy;
        g_X[xoff] = nx;
        g_X[xoff + 1] = ny;
        if (last) { dout[xoff] = nx; dout[xoff + 1] = ny; }
    }
}

// ------------------------------------------------------------------
extern "C" void kernel_launch(void* const* d_in, const int* in_sizes, int n_in,
                              void* d_out, int out_size) {
    const float* q0  = (const float*)d_in[0];
    const float* tpl = (const float*)d_in[1];
    const float* cp  = (const float*)d_in[2];
    const float* W1  = (const float*)d_in[3];
    const float* b1  = (const float*)d_in[4];
    const float* W2  = (const float*)d_in[5];
    const float* b2  = (const float*)d_in[6];
    const float* W3  = (const float*)d_in[7];
    const float* b3  = (const float*)d_in[8];
    float* out = (float*)d_out;
    (void)in_sizes; (void)n_in; (void)out_size;

    init_kernel<<<256, 256>>>(q0, tpl, cp);
    for (int k = 0; k < NSTEP; k++)
        shoot_kernel<<<NB * NCP, 64>>>(k, W1, b1, W2, b2, W3, b3);
    for (int k = 0; k <= NSTEP; k++)
        flow_kernel<<<NB * (NTPL / 32), 128>>>(k, (k == NSTEP) ? 1 : 0, out,
                                               W1, b1, W2, b2, W3, b3);
}

// round 2
// speedup vs baseline: 1.6826x; 1.6826x over previous
#include <cuda_runtime.h>

#define NB    16
#define NCP   64
#define NTPL  2048
#define HD    10
#define NSTEP 6
#define DTC   0.2f
#define LOG2E 1.4426950408889634f

typedef unsigned long long ull;

// ---- scratch (static device globals; no allocation) ----
__device__ float g_P[NSTEP + 1][NB * NCP * 2];
__device__ float g_Q[NSTEP + 1][NB * NCP * 2];
__device__ float g_X[NB * NTPL * 2];

// ---------------- packed f32x2 helpers ----------------
__device__ __forceinline__ ull pack2(float lo, float hi) {
    ull d; asm("mov.b64 %0, {%1,%2};" : "=l"(d) : "f"(lo), "f"(hi)); return d;
}
__device__ __forceinline__ void unpack2(ull d, float& lo, float& hi) {
    asm("mov.b64 {%0,%1}, %2;" : "=f"(lo), "=f"(hi) : "l"(d));
}
__device__ __forceinline__ ull fma2(ull a, ull b, ull c) {
    ull d; asm("fma.rn.f32x2 %0, %1, %2, %3;" : "=l"(d) : "l"(a), "l"(b), "l"(c)); return d;
}
__device__ __forceinline__ ull add2(ull a, ull b) {
    ull d; asm("add.rn.f32x2 %0, %1, %2;" : "=l"(d) : "l"(a), "l"(b)); return d;
}
__device__ __forceinline__ float tanhfast(float x) {
    float y; asm("tanh.approx.f32 %0, %1;" : "=f"(y) : "f"(x)); return y;
}
__device__ __forceinline__ float ex2f(float x) {
    float y; asm("ex2.approx.f32 %0, %1;" : "=f"(y) : "f"(x)); return y;
}

__device__ __forceinline__ float ftanh(float x) {
    // exact-path tanh for the shooting phase
    float e = __expf(2.0f * x);
    return 1.0f - __fdividef(2.0f, e + 1.0f);
}

// ------------------------------------------------------------------
// init: broadcast template -> g_X, control points -> g_P[0], q0 -> g_Q[0]
// ------------------------------------------------------------------
__global__ void init_kernel(const float* __restrict__ q0,
                            const float* __restrict__ tpl,
                            const float* __restrict__ cp) {
    int idx = blockIdx.x * blockDim.x + threadIdx.x;
    if (idx < NB * NTPL * 2) g_X[idx] = tpl[idx & (NTPL * 2 - 1)];
    if (idx < NB * NCP * 2) {
        g_Q[0][idx] = q0[idx];
        g_P[0][idx] = cp[idx & (NCP * 2 - 1)];
    }
}

// ------------------------------------------------------------------
// MLP forward + 2-tangent JVP (tangent dirs = rows da, db of W1) — exact tanh
// ------------------------------------------------------------------
__device__ __forceinline__ void mlp_jac(
    float z0, float z1, float z2, float z3, int da, int db,
    const float* __restrict__ sW1, const float* __restrict__ sb1,
    const float* __restrict__ sW2, const float* __restrict__ sb2,
    const float* __restrict__ sW3, const float* __restrict__ sb3,
    float o[3], float ja[3], float jb[3]) {
    float h1[HD], ta[HD], tb[HD];
#pragma unroll
    for (int n = 0; n < HD; n++) {
        float u = sb1[n] + z0 * sW1[n] + z1 * sW1[10 + n] + z2 * sW1[20 + n] + z3 * sW1[30 + n];
        float h = ftanh(u);
        float g = 1.0f - h * h;
        h1[n] = h;
        ta[n] = g * sW1[da * 10 + n];
        tb[n] = g * sW1[db * 10 + n];
    }
    float u2[HD], s2a[HD], s2b[HD];
#pragma unroll
    for (int m = 0; m < HD; m++) { u2[m] = sb2[m]; s2a[m] = 0.f; s2b[m] = 0.f; }
#pragma unroll
    for (int n = 0; n < HD; n++) {
        float h = h1[n], aa = ta[n], bb = tb[n];
#pragma unroll
        for (int m = 0; m < HD; m++) {
            float w = sW2[n * 10 + m];
            u2[m] += h * w;
            s2a[m] += aa * w;
            s2b[m] += bb * w;
        }
    }
#pragma unroll
    for (int c = 0; c < 3; c++) { o[c] = sb3[c]; ja[c] = 0.f; jb[c] = 0.f; }
#pragma unroll
    for (int m = 0; m < HD; m++) {
        float h = ftanh(u2[m]);
        float g = 1.0f - h * h;
        float aa = s2a[m] * g, bb = s2b[m] * g;
#pragma unroll
        for (int c = 0; c < 3; c++) {
            float w = sW3[m * 3 + c];
            o[c] += h * w;
            ja[c] += aa * w;
            jb[c] += bb * w;
        }
    }
}

// ------------------------------------------------------------------
// shooting step: one block per (batch,a) point; 128 threads = 64 j x 2 halves.
// The symmetric kernel splits per MLP direction; each half's contribution
// to dh_dq and dH/dp is separable, so each thread does ONE mlp_jac.
// ------------------------------------------------------------------
__global__ void shoot_kernel(int k,
    const float* __restrict__ W1, const float* __restrict__ b1,
    const float* __restrict__ W2, const float* __restrict__ b2,
    const float* __restrict__ W3, const float* __restrict__ b3) {
    __shared__ float sW1[40], sb1[10], sW2[100], sb2[10], sW3[30], sb3[3];
    __shared__ float red[4][4];
    int t = threadIdx.x;
    for (int i = t; i < 40; i += 128) sW1[i] = W1[i];
    for (int i = t; i < 100; i += 128) sW2[i] = W2[i];
    for (int i = t; i < 30; i += 128) sW3[i] = W3[i];
    if (t < 10) { sb1[t] = b1[t]; sb2[t] = b2[t]; }
    if (t < 3) sb3[t] = b3[t];
    __syncthreads();

    int blk = blockIdx.x;
    int b = blk >> 6, a = blk & 63;
    const float* P = g_P[k];
    const float* Q = g_Q[k];
    float pax = P[(b * NCP + a) * 2 + 0], pay = P[(b * NCP + a) * 2 + 1];
    float qax = Q[(b * NCP + a) * 2 + 0], qay = Q[(b * NCP + a) * 2 + 1];
    int j = t & 63, half = t >> 6;
    float pjx = P[(b * NCP + j) * 2 + 0], pjy = P[(b * NCP + j) * 2 + 1];
    float qjx = Q[(b * NCP + j) * 2 + 0], qjy = Q[(b * NCP + j) * 2 + 1];

    // half 0: m(pa, pj), tangent dirs 0,1 ; half 1: m(pj, pa), tangent dirs 2,3
    float z0 = half ? pjx : pax, z1 = half ? pjy : pay;
    float z2 = half ? pax : pjx, z3 = half ? pay : pjy;
    int da = half * 2, db = half * 2 + 1;

    float o[3], ja[3], jb[3];
    mlp_jac(z0, z1, z2, z3, da, db, sW1, sb1, sW2, sb2, sW3, sb3, o, ja, jb);

    float ea = __expf(o[1]), eb = __expf(o[2]);
    // half-contribution to v = K q  (K = 0.5*(S1+S2))
    float vqx = 0.5f * (ea * qjx + o[0] * qjy);
    float vqy = 0.5f * (o[0] * qjx + eb * qjy);
    // half-contribution to grad_p H
    float cw = qax * qjy + qay * qjx;
    float w1 = ea * (qax * qjx), w2 = eb * (qay * qjy);
    float gpx = 0.5f * (cw * ja[0] + w1 * ja[1] + w2 * ja[2]);
    float gpy = 0.5f * (cw * jb[0] + w1 * jb[1] + w2 * jb[2]);

#pragma unroll
    for (int off = 16; off > 0; off >>= 1) {
        vqx += __shfl_down_sync(0xffffffffu, vqx, off);
        vqy += __shfl_down_sync(0xffffffffu, vqy, off);
        gpx += __shfl_down_sync(0xffffffffu, gpx, off);
        gpy += __shfl_down_sync(0xffffffffu, gpy, off);
    }
    if ((t & 31) == 0) {
        int w = t >> 5;
        red[w][0] = vqx; red[w][1] = vqy; red[w][2] = gpx; red[w][3] = gpy;
    }
    __syncthreads();
    if (t == 0) {
        float VX = red[0][0] + red[1][0] + red[2][0] + red[3][0];
        float VY = red[0][1] + red[1][1] + red[2][1] + red[3][1];
        float GX = red[0][2] + red[1][2] + red[2][2] + red[3][2];
        float GY = red[0][3] + red[1][3] + red[2][3] + red[3][3];
        float* Pn = g_P[k + 1];
        float* Qn = g_Q[k + 1];
        Pn[(b * NCP + a) * 2 + 0] = pax + DTC * VX;
        Pn[(b * NCP + a) * 2 + 1] = pay + DTC * VY;
        Qn[(b * NCP + a) * 2 + 0] = qax - DTC * GX;
        Qn[(b * NCP + a) * 2 + 1] = qay - DTC * GY;
    }
}

// ------------------------------------------------------------------
// packed forward MLP: layer-1 preactivation u1p (5 x f32x2) given;
// W2 packed by output-pair (50 x f32x2), W3 cols 1,2 prescaled by log2e
// so outputs o12 feed ex2 directly. tanh via MUFU.TANH.
// ------------------------------------------------------------------
__device__ __forceinline__ void mlp2(
    const ull u1p[5], const ull W2p[50], const ull b2p[5],
    const float W3c0[10], const ull W3p12[10],
    float b3c0, ull b3p12,
    float& o0, ull& o12) {
    ull u2p[5];
#pragma unroll
    for (int i = 0; i < 5; i++) u2p[i] = b2p[i];
#pragma unroll
    for (int i = 0; i < 5; i++) {
        float lo, hi; unpack2(u1p[i], lo, hi);
        float h0 = tanhfast(lo), h1 = tanhfast(hi);
        ull hp0 = pack2(h0, h0), hp1 = pack2(h1, h1);
        int n0 = (2 * i) * 5, n1 = (2 * i + 1) * 5;
#pragma unroll
        for (int m = 0; m < 5; m++) u2p[m] = fma2(hp0, W2p[n0 + m], u2p[m]);
#pragma unroll
        for (int m = 0; m < 5; m++) u2p[m] = fma2(hp1, W2p[n1 + m], u2p[m]);
    }
    o0 = b3c0; o12 = b3p12;
#pragma unroll
    for (int i = 0; i < 5; i++) {
        float lo, hi; unpack2(u2p[i], lo, hi);
        float h0 = tanhfast(lo), h1 = tanhfast(hi);
        ull hp0 = pack2(h0, h0), hp1 = pack2(h1, h1);
        o12 = fma2(hp0, W3p12[2 * i], o12);
        o12 = fma2(hp1, W3p12[2 * i + 1], o12);
        o0 = fmaf(h1, W3c0[2 * i + 1], fmaf(h0, W3c0[2 * i], o0));
    }
}

// ------------------------------------------------------------------
// flow step: x += DT * K(x, p_k) q_k.  128 thr/block = 32 points x 4 j-splits.
// ------------------------------------------------------------------
__global__ void __launch_bounds__(128, 2) flow_kernel(int k, int last, float* __restrict__ dout,
    const float* __restrict__ W1, const float* __restrict__ b1,
    const float* __restrict__ W2, const float* __restrict__ b2,
    const float* __restrict__ W3, const float* __restrict__ b3) {
    __shared__ ull sA[NCP][5];   // packed b1 + pj.W1[0:2]  (pj in x-slots)
    __shared__ ull sB[NCP][5];   // packed      pj.W1[2:4]  (pj in y-slots)
    __shared__ float sQx[NCP], sQy[NCP];
    int t = threadIdx.x;
    int blk = blockIdx.x;
    int b = blk >> 6;
    int pt0 = (blk & 63) << 5;
    const float* P = g_P[k];
    const float* Q = g_Q[k];
    if (t < NCP) {
        float px = P[(b * NCP + t) * 2 + 0], py = P[(b * NCP + t) * 2 + 1];
#pragma unroll
        for (int i = 0; i < 5; i++) {
            int n0 = 2 * i, n1 = 2 * i + 1;
            float a0 = __ldg(&b1[n0]) + px * __ldg(&W1[n0]) + py * __ldg(&W1[10 + n0]);
            float a1 = __ldg(&b1[n1]) + px * __ldg(&W1[n1]) + py * __ldg(&W1[10 + n1]);
            sA[t][i] = pack2(a0, a1);
            float c0 = px * __ldg(&W1[20 + n0]) + py * __ldg(&W1[30 + n0]);
            float c1 = px * __ldg(&W1[20 + n1]) + py * __ldg(&W1[30 + n1]);
            sB[t][i] = pack2(c0, c1);
        }
        sQx[t] = Q[(b * NCP + t) * 2 + 0];
        sQy[t] = Q[(b * NCP + t) * 2 + 1];
    }

    // weights resident in registers across the whole j-loop
    const ull* W2v = reinterpret_cast<const ull*>(W2);
    const ull* b2v = reinterpret_cast<const ull*>(b2);
    ull W2p[50];
#pragma unroll
    for (int i = 0; i < 50; i++) W2p[i] = __ldg(&W2v[i]);
    ull b2p[5];
#pragma unroll
    for (int i = 0; i < 5; i++) b2p[i] = __ldg(&b2v[i]);
    float W3c0[10];
    ull W3p12[10];
#pragma unroll
    for (int m = 0; m < HD; m++) {
        W3c0[m] = __ldg(&W3[m * 3 + 0]);
        W3p12[m] = pack2(LOG2E * __ldg(&W3[m * 3 + 1]), LOG2E * __ldg(&W3[m * 3 + 2]));
    }
    float b3c0 = __ldg(&b3[0]);
    ull b3p12 = pack2(LOG2E * __ldg(&b3[1]), LOG2E * __ldg(&b3[2]));

    int lp = t >> 2, quarter = t & 3;
    int i0 = pt0 + lp;
    int xoff = (b * NTPL + i0) * 2;
    float xx = g_X[xoff], xy = g_X[xoff + 1];
    ull axp[5], bxp[5];
#pragma unroll
    for (int i = 0; i < 5; i++) {
        int n0 = 2 * i, n1 = 2 * i + 1;
        float a0 = __ldg(&b1[n0]) + xx * __ldg(&W1[n0]) + xy * __ldg(&W1[10 + n0]);
        float a1 = __ldg(&b1[n1]) + xx * __ldg(&W1[n1]) + xy * __ldg(&W1[10 + n1]);
        axp[i] = pack2(a0, a1);
        float c0 = xx * __ldg(&W1[20 + n0]) + xy * __ldg(&W1[30 + n0]);
        float c1 = xx * __ldg(&W1[20 + n1]) + xy * __ldg(&W1[30 + n1]);
        bxp[i] = pack2(c0, c1);
    }
    __syncthreads();

    float vx = 0.f, vy = 0.f;
    int jbase = quarter << 4;
#pragma unroll 1
    for (int jj = 0; jj < 16; jj++) {
        int j = jbase + jj;
        ull u1[5];
#pragma unroll
        for (int i = 0; i < 5; i++) u1[i] = add2(axp[i], sB[j][i]);  // m(x, pj)
        float a0; ull a12;
        mlp2(u1, W2p, b2p, W3c0, W3p12, b3c0, b3p12, a0, a12);
#pragma unroll
        for (int i = 0; i < 5; i++) u1[i] = add2(sA[j][i], bxp[i]);  // m(pj, x)
        float c0; ull c12;
        mlp2(u1, W2p, b2p, W3c0, W3p12, b3c0, b3p12, c0, c12);
        float a1, a2, c1, c2;
        unpack2(a12, a1, a2);
        unpack2(c12, c1, c2);
        float Kxx = 0.5f * (ex2f(a1) + ex2f(c1));
        float Kyy = 0.5f * (ex2f(a2) + ex2f(c2));
        float Kxy = 0.5f * (a0 + c0);
        float qx = sQx[j], qy = sQy[j];
        vx += Kxx * qx + Kxy * qy;
        vy += Kxy * qx + Kyy * qy;
    }
    // combine the 4 j-splits (adjacent lanes)
    vx += __shfl_xor_sync(0xffffffffu, vx, 1);
    vy += __shfl_xor_sync(0xffffffffu, vy, 1);
    vx += __shfl_xor_sync(0xffffffffu, vx, 2);
    vy += __shfl_xor_sync(0xffffffffu, vy, 2);
    if (quarter == 0) {
        float nx = xx + DTC * vx;
        float ny = xy + DTC * vy;
        g_X[xoff] = nx;
        g_X[xoff + 1] = ny;
        if (last) { dout[xoff] = nx; dout[xoff + 1] = ny; }
    }
}

// ------------------------------------------------------------------
extern "C" void kernel_launch(void* const* d_in, const int* in_sizes, int n_in,
                              void* d_out, int out_size) {
    const float* q0  = (const float*)d_in[0];
    const float* tpl = (const float*)d_in[1];
    const float* cp  = (const float*)d_in[2];
    const float* W1  = (const float*)d_in[3];
    const float* b1  = (const float*)d_in[4];
    const float* W2  = (const float*)d_in[5];
    const float* b2  = (const float*)d_in[6];
    const float* W3  = (const float*)d_in[7];
    const float* b3  = (const float*)d_in[8];
    float* out = (float*)d_out;
    (void)in_sizes; (void)n_in; (void)out_size;

    init_kernel<<<256, 256>>>(q0, tpl, cp);
    for (int k = 0; k < NSTEP; k++)
        shoot_kernel<<<NB * NCP, 128>>>(k, W1, b1, W2, b2, W3, b3);
    for (int k = 0; k <= NSTEP; k++)
        flow_kernel<<<NB * (NTPL / 32), 128>>>(k, (k == NSTEP) ? 1 : 0, out,
                                               W1, b1, W2, b2, W3, b3);
}

// round 3
// speedup vs baseline: 1.9984x; 1.1877x over previous
#include <cuda_runtime.h>

#define NB    16
#define NCP   64
#define NTPL  2048
#define HD    10
#define NSTEP 6
#define DTC   0.2f
#define LOG2E 1.4426950408889634f

typedef unsigned long long ull;

// ---- scratch (static device globals; no allocation) ----
__device__ float2 g_P[NSTEP + 1][NB * NCP];
__device__ float2 g_Q[NSTEP + 1][NB * NCP];
__device__ unsigned g_bar_count;   // zero-initialized; self-resetting
__device__ unsigned g_bar_gen;     // monotonically increasing across replays

// ---------------- packed f32x2 helpers ----------------
__device__ __forceinline__ ull pack2(float lo, float hi) {
    ull d; asm("mov.b64 %0, {%1,%2};" : "=l"(d) : "f"(lo), "f"(hi)); return d;
}
__device__ __forceinline__ void unpack2(ull d, float& lo, float& hi) {
    asm("mov.b64 {%0,%1}, %2;" : "=f"(lo), "=f"(hi) : "l"(d));
}
__device__ __forceinline__ ull fma2(ull a, ull b, ull c) {
    ull d; asm("fma.rn.f32x2 %0, %1, %2, %3;" : "=l"(d) : "l"(a), "l"(b), "l"(c)); return d;
}
__device__ __forceinline__ ull add2(ull a, ull b) {
    ull d; asm("add.rn.f32x2 %0, %1, %2;" : "=l"(d) : "l"(a), "l"(b)); return d;
}
__device__ __forceinline__ float tanhfast(float x) {
    float y; asm("tanh.approx.f32 %0, %1;" : "=f"(y) : "f"(x)); return y;
}
__device__ __forceinline__ float ex2f(float x) {
    float y; asm("ex2.approx.f32 %0, %1;" : "=f"(y) : "f"(x)); return y;
}

// ---------------- software grid barrier (all CTAs resident) ----------------
__device__ __forceinline__ void grid_bar() {
    __syncthreads();
    if (threadIdx.x == 0) {
        __threadfence();
        unsigned gen = *(volatile unsigned*)&g_bar_gen;
        unsigned prev = atomicAdd(&g_bar_count, 1u);
        if (prev == gridDim.x - 1) {
            g_bar_count = 0;
            __threadfence();
            atomicExch(&g_bar_gen, gen + 1u);
        } else {
            while (*(volatile unsigned*)&g_bar_gen == gen) { }
            __threadfence();
        }
    }
    __syncthreads();
}

// ------------------------------------------------------------------
// MLP forward + 2-tangent JVP (tangent dirs = rows da, db of W1)
// ------------------------------------------------------------------
__device__ __forceinline__ void mlp_jac(
    float z0, float z1, float z2, float z3, int da, int db,
    const float* __restrict__ sW1, const float* __restrict__ sb1,
    const float* __restrict__ sW2, const float* __restrict__ sb2,
    const float* __restrict__ sW3, const float* __restrict__ sb3,
    float o[3], float ja[3], float jb[3]) {
    float h1[HD], ta[HD], tb[HD];
#pragma unroll
    for (int n = 0; n < HD; n++) {
        float u = sb1[n] + z0 * sW1[n] + z1 * sW1[10 + n] + z2 * sW1[20 + n] + z3 * sW1[30 + n];
        float h = tanhfast(u);
        float g = 1.0f - h * h;
        h1[n] = h;
        ta[n] = g * sW1[da * 10 + n];
        tb[n] = g * sW1[db * 10 + n];
    }
    float u2[HD], s2a[HD], s2b[HD];
#pragma unroll
    for (int m = 0; m < HD; m++) { u2[m] = sb2[m]; s2a[m] = 0.f; s2b[m] = 0.f; }
#pragma unroll
    for (int n = 0; n < HD; n++) {
        float h = h1[n], aa = ta[n], bb = tb[n];
#pragma unroll
        for (int m = 0; m < HD; m++) {
            float w = sW2[n * 10 + m];
            u2[m] += h * w;
            s2a[m] += aa * w;
            s2b[m] += bb * w;
        }
    }
#pragma unroll
    for (int c = 0; c < 3; c++) { o[c] = sb3[c]; ja[c] = 0.f; jb[c] = 0.f; }
#pragma unroll
    for (int m = 0; m < HD; m++) {
        float h = tanhfast(u2[m]);
        float g = 1.0f - h * h;
        float aa = s2a[m] * g, bb = s2b[m] * g;
#pragma unroll
        for (int c = 0; c < 3; c++) {
            float w = sW3[m * 3 + c];
            o[c] += h * w;
            ja[c] += aa * w;
            jb[c] += bb * w;
        }
    }
}

// ------------------------------------------------------------------
// all 6 shooting steps in ONE persistent kernel.
// 512 CTAs x 128 thr; CTA c: batch b = c>>5, a-points {2(c&31), 2(c&31)+1}.
// threads: j = t&63, half = t>>6 (MLP direction). grid barrier between steps.
// __launch_bounds__(128,4) guarantees <=128 regs -> 4 CTAs/SM -> all resident.
// ------------------------------------------------------------------
__global__ void __launch_bounds__(128, 4) shoot_all(
    const float* __restrict__ q0, const float* __restrict__ cp,
    const float* __restrict__ W1, const float* __restrict__ b1,
    const float* __restrict__ W2, const float* __restrict__ b2,
    const float* __restrict__ W3, const float* __restrict__ b3) {
    __shared__ float sW1[40], sb1[10], sW2[100], sb2[10], sW3[30], sb3[3];
    __shared__ float red[2][4][4];
    int t = threadIdx.x;
    for (int i = t; i < 40; i += 128) sW1[i] = W1[i];
    for (int i = t; i < 100; i += 128) sW2[i] = W2[i];
    for (int i = t; i < 30; i += 128) sW3[i] = W3[i];
    if (t < 10) { sb1[t] = b1[t]; sb2[t] = b2[t]; }
    if (t < 3) sb3[t] = b3[t];
    __syncthreads();

    int c = blockIdx.x;
    int b = c >> 5;
    int a0 = (c & 31) << 1;
    int j = t & 63, half = t >> 6;
    const float2* cp2 = (const float2*)cp;
    const float2* q02 = (const float2*)q0;

    for (int k = 0; k < NSTEP; k++) {
        float2 pj, qj;
        if (k == 0) { pj = cp2[j]; qj = q02[b * NCP + j]; }
        else        { pj = g_P[k][b * NCP + j]; qj = g_Q[k][b * NCP + j]; }

        float2 pas[2], qas[2];
#pragma unroll
        for (int aa = 0; aa < 2; aa++) {
            int a = a0 + aa;
            float2 pa, qa;
            if (k == 0) { pa = cp2[a]; qa = q02[b * NCP + a]; }
            else        { pa = g_P[k][b * NCP + a]; qa = g_Q[k][b * NCP + a]; }
            pas[aa] = pa; qas[aa] = qa;

            // half 0: m(pa,pj), tangents wrt inputs 0,1; half 1: m(pj,pa), tangents 2,3
            float z0 = half ? pj.x : pa.x, z1 = half ? pj.y : pa.y;
            float z2 = half ? pa.x : pj.x, z3 = half ? pa.y : pj.y;
            int da = half * 2, db = half * 2 + 1;

            float o[3], ja[3], jb[3];
            mlp_jac(z0, z1, z2, z3, da, db, sW1, sb1, sW2, sb2, sW3, sb3, o, ja, jb);

            float ea = __expf(o[1]), eb = __expf(o[2]);
            float vqx = 0.5f * (ea * qj.x + o[0] * qj.y);
            float vqy = 0.5f * (o[0] * qj.x + eb * qj.y);
            float cw = qa.x * qj.y + qa.y * qj.x;
            float w1 = ea * (qa.x * qj.x), w2 = eb * (qa.y * qj.y);
            float gpx = 0.5f * (cw * ja[0] + w1 * ja[1] + w2 * ja[2]);
            float gpy = 0.5f * (cw * jb[0] + w1 * jb[1] + w2 * jb[2]);

#pragma unroll
            for (int off = 16; off > 0; off >>= 1) {
                vqx += __shfl_down_sync(0xffffffffu, vqx, off);
                vqy += __shfl_down_sync(0xffffffffu, vqy, off);
                gpx += __shfl_down_sync(0xffffffffu, gpx, off);
                gpy += __shfl_down_sync(0xffffffffu, gpy, off);
            }
            if ((t & 31) == 0) {
                int w = t >> 5;
                red[aa][w][0] = vqx; red[aa][w][1] = vqy;
                red[aa][w][2] = gpx; red[aa][w][3] = gpy;
            }
        }
        __syncthreads();
        if (t == 0) {
#pragma unroll
            for (int aa = 0; aa < 2; aa++) {
                int a = a0 + aa;
                float VX = red[aa][0][0] + red[aa][1][0] + red[aa][2][0] + red[aa][3][0];
                float VY = red[aa][0][1] + red[aa][1][1] + red[aa][2][1] + red[aa][3][1];
                float GX = red[aa][0][2] + red[aa][1][2] + red[aa][2][2] + red[aa][3][2];
                float GY = red[aa][0][3] + red[aa][1][3] + red[aa][2][3] + red[aa][3][3];
                g_P[k + 1][b * NCP + a] = make_float2(pas[aa].x + DTC * VX, pas[aa].y + DTC * VY);
                g_Q[k + 1][b * NCP + a] = make_float2(qas[aa].x - DTC * GX, qas[aa].y - DTC * GY);
                if (k == 0) {  // materialize step-0 state for the flow kernel
                    g_P[0][b * NCP + a] = pas[aa];
                    g_Q[0][b * NCP + a] = qas[aa];
                }
            }
        }
        if (k < NSTEP - 1) grid_bar();
    }
}

// ------------------------------------------------------------------
// packed forward MLP (layer-1 preactivation given); W2 packed by output
// pair; W3 cols 1,2 prescaled by log2e so o12 feeds ex2 directly.
// ------------------------------------------------------------------
__device__ __forceinline__ void mlp2(
    const ull u1p[5], const ull W2p[50], const ull b2p[5],
    const float W3c0[10], const ull W3p12[10],
    float b3c0, ull b3p12,
    float& o0, ull& o12) {
    ull u2p[5];
#pragma unroll
    for (int i = 0; i < 5; i++) u2p[i] = b2p[i];
#pragma unroll
    for (int i = 0; i < 5; i++) {
        float lo, hi; unpack2(u1p[i], lo, hi);
        float h0 = tanhfast(lo), h1 = tanhfast(hi);
        ull hp0 = pack2(h0, h0), hp1 = pack2(h1, h1);
        int n0 = (2 * i) * 5, n1 = (2 * i + 1) * 5;
#pragma unroll
        for (int m = 0; m < 5; m++) u2p[m] = fma2(hp0, W2p[n0 + m], u2p[m]);
#pragma unroll
        for (int m = 0; m < 5; m++) u2p[m] = fma2(hp1, W2p[n1 + m], u2p[m]);
    }
    o0 = b3c0; o12 = b3p12;
#pragma unroll
    for (int i = 0; i < 5; i++) {
        float lo, hi; unpack2(u2p[i], lo, hi);
        float h0 = tanhfast(lo), h1 = tanhfast(hi);
        ull hp0 = pack2(h0, h0), hp1 = pack2(h1, h1);
        o12 = fma2(hp0, W3p12[2 * i], o12);
        o12 = fma2(hp1, W3p12[2 * i + 1], o12);
        o0 = fmaf(h1, W3c0[2 * i + 1], fmaf(h0, W3c0[2 * i], o0));
    }
}

// ------------------------------------------------------------------
// all 7 flow steps in ONE kernel: x stays in registers across steps.
// 1024 CTAs x 128 thr = 32 points x 4 j-splits; j interleaved mod 4 so the
// 4 splits hit consecutive sA rows (conflict-free LDS.64).
// ------------------------------------------------------------------
__global__ void __launch_bounds__(128, 2) flow_all(
    const float* __restrict__ tpl, float* __restrict__ dout,
    const float* __restrict__ W1, const float* __restrict__ b1,
    const float* __restrict__ W2, const float* __restrict__ b2,
    const float* __restrict__ W3, const float* __restrict__ b3) {
    __shared__ ull sA[NCP][5];   // packed b1 + pj.W1[0:2]
    __shared__ ull sB[NCP][5];   // packed      pj.W1[2:4]
    __shared__ float sQx[NCP], sQy[NCP];   // 0.5*q folded in
    __shared__ float sW1[40], sb1[10];
    int t = threadIdx.x;
    int blk = blockIdx.x;
    int b = blk >> 6;
    int pt0 = (blk & 63) << 5;
    if (t < 40) sW1[t] = W1[t];
    if (t < 10) sb1[t] = b1[t];

    // weights resident in registers for the whole kernel
    const ull* W2v = (const ull*)W2;
    const ull* b2v = (const ull*)b2;
    ull W2p[50];
#pragma unroll
    for (int i = 0; i < 50; i++) W2p[i] = __ldg(&W2v[i]);
    ull b2p[5];
#pragma unroll
    for (int i = 0; i < 5; i++) b2p[i] = __ldg(&b2v[i]);
    float W3c0[10];
    ull W3p12[10];
#pragma unroll
    for (int m = 0; m < HD; m++) {
        W3c0[m] = __ldg(&W3[m * 3 + 0]);
        W3p12[m] = pack2(LOG2E * __ldg(&W3[m * 3 + 1]), LOG2E * __ldg(&W3[m * 3 + 2]));
    }
    float b3c0 = __ldg(&b3[0]);
    ull b3p12 = pack2(LOG2E * __ldg(&b3[1]), LOG2E * __ldg(&b3[2]));

    int lp = t >> 2, quarter = t & 3;
    int i0 = pt0 + lp;
    float2 x = __ldg(&((const float2*)tpl)[i0]);

    for (int k = 0; k <= NSTEP; k++) {
        __syncthreads();   // prior iteration's reads of sA/sB done
        if (t < NCP) {
            float2 p = g_P[k][b * NCP + t];
            float2 q = g_Q[k][b * NCP + t];
#pragma unroll
            for (int i = 0; i < 5; i++) {
                int n0 = 2 * i, n1 = n0 + 1;
                sA[t][i] = pack2(sb1[n0] + p.x * sW1[n0] + p.y * sW1[10 + n0],
                                 sb1[n1] + p.x * sW1[n1] + p.y * sW1[10 + n1]);
                sB[t][i] = pack2(p.x * sW1[20 + n0] + p.y * sW1[30 + n0],
                                 p.x * sW1[20 + n1] + p.y * sW1[30 + n1]);
            }
            sQx[t] = 0.5f * q.x;
            sQy[t] = 0.5f * q.y;
        }
        // per-thread layer-1 parts for current x
        ull axp[5], bxp[5];
#pragma unroll
        for (int i = 0; i < 5; i++) {
            int n0 = 2 * i, n1 = n0 + 1;
            axp[i] = pack2(sb1[n0] + x.x * sW1[n0] + x.y * sW1[10 + n0],
                           sb1[n1] + x.x * sW1[n1] + x.y * sW1[10 + n1]);
            bxp[i] = pack2(x.x * sW1[20 + n0] + x.y * sW1[30 + n0],
                           x.x * sW1[20 + n1] + x.y * sW1[30 + n1]);
        }
        __syncthreads();

        float vx = 0.f, vy = 0.f;
#pragma unroll 1
        for (int jj = 0; jj < 16; jj++) {
            int j = (jj << 2) | quarter;
            ull u1[5];
#pragma unroll
            for (int i = 0; i < 5; i++) u1[i] = add2(axp[i], sB[j][i]);  // m(x, pj)
            float a0; ull a12;
            mlp2(u1, W2p, b2p, W3c0, W3p12, b3c0, b3p12, a0, a12);
#pragma unroll
            for (int i = 0; i < 5; i++) u1[i] = add2(sA[j][i], bxp[i]);  // m(pj, x)
            float c0; ull c12;
            mlp2(u1, W2p, b2p, W3c0, W3p12, b3c0, b3p12, c0, c12);
            float a1, a2, c1, c2;
            unpack2(a12, a1, a2);
            unpack2(c12, c1, c2);
            float s0 = a0 + c0;
            float qx2 = sQx[j], qy2 = sQy[j];
            vx = fmaf(ex2f(a1), qx2, vx);
            vx = fmaf(ex2f(c1), qx2, vx);
            vx = fmaf(s0, qy2, vx);
            vy = fmaf(s0, qx2, vy);
            vy = fmaf(ex2f(a2), qy2, vy);
            vy = fmaf(ex2f(c2), qy2, vy);
        }
        // combine the 4 j-splits; xor pattern leaves the sum in ALL 4 lanes
        vx += __shfl_xor_sync(0xffffffffu, vx, 1);
        vy += __shfl_xor_sync(0xffffffffu, vy, 1);
        vx += __shfl_xor_sync(0xffffffffu, vx, 2);
        vy += __shfl_xor_sync(0xffffffffu, vy, 2);
        x.x = fmaf(DTC, vx, x.x);
        x.y = fmaf(DTC, vy, x.y);
    }
    if (quarter == 0) ((float2*)dout)[b * NTPL + i0] = x;
}

// ------------------------------------------------------------------
extern "C" void kernel_launch(void* const* d_in, const int* in_sizes, int n_in,
                              void* d_out, int out_size) {
    const float* q0  = (const float*)d_in[0];
    const float* tpl = (const float*)d_in[1];
    const float* cp  = (const float*)d_in[2];
    const float* W1  = (const float*)d_in[3];
    const float* b1  = (const float*)d_in[4];
    const float* W2  = (const float*)d_in[5];
    const float* b2  = (const float*)d_in[6];
    const float* W3  = (const float*)d_in[7];
    const float* b3  = (const float*)d_in[8];
    float* out = (float*)d_out;
    (void)in_sizes; (void)n_in; (void)out_size;

    shoot_all<<<512, 128>>>(q0, cp, W1, b1, W2, b2, W3, b3);
    flow_all<<<NB * (NTPL / 32), 128>>>(tpl, out, W1, b1, W2, b2, W3, b3);
}